// round 11
// baseline (speedup 1.0000x reference)
#include <cuda_runtime.h>
#include <cstdint>

// Problem constants (B=4096, L=64, C=7, H=32, K=2)
#define LSEQ     64
#define CDIM     7
#define HDIM     32
#define CH       224          // C*H
#define NSTEP    126          // (L-1)*K
#define HSTEP    0.5f
#define BT       16           // batch per CTA
#define GPAIRS   8            // pairs per CTA
#define THREADS  448          // 224 j2 x 2 k-halves

typedef unsigned long long u64;

// diffs scratch in global (L2-resident): [2048 pairs][63][7]
__device__ u64 g_diffs[2048 * 63 * CDIM];

// ---------- packed f32x2 helpers ----------
__device__ __forceinline__ u64 pk2(float a, float b){
    u64 r; asm("mov.b64 %0,{%1,%2};" : "=l"(r) : "f"(a), "f"(b)); return r;
}
__device__ __forceinline__ float2 upk2(u64 v){
    float2 f; asm("mov.b64 {%0,%1},%2;" : "=f"(f.x), "=f"(f.y) : "l"(v)); return f;
}
__device__ __forceinline__ u64 fma2(u64 a, u64 b, u64 c){
    u64 d; asm("fma.rn.f32x2 %0,%1,%2,%3;" : "=l"(d) : "l"(a), "l"(b), "l"(c)); return d;
}
__device__ __forceinline__ u64 add2(u64 a, u64 b){
    u64 d; asm("add.rn.f32x2 %0,%1,%2;" : "=l"(d) : "l"(a), "l"(b)); return d;
}
__device__ __forceinline__ u64 mul2(u64 a, u64 b){
    u64 d; asm("mul.rn.f32x2 %0,%1,%2;" : "=l"(d) : "l"(a), "l"(b)); return d;
}

__device__ __forceinline__ float softplus1(float x){
    return (x > 20.f) ? x : __logf(1.f + __expf(x));
}
__device__ __forceinline__ float tanh1(float x){
    float e = __expf(2.f * x);
    return 1.f - __fdividef(2.f, e + 1.f);
}
__device__ __forceinline__ u64 tanh2v(u64 v){
    float2 f = upk2(v); return pk2(tanh1(f.x), tanh1(f.y));
}

// ---------- shared memory layout (~38.5 KB -> 2 CTAs/SM) ----------
struct __align__(16) SM {
    u64 g    [GPAIRS * CH];          // 14336 B
    u64 h1   [GPAIRS * HDIM];
    u64 z    [GPAIRS * HDIM];
    u64 ztmp [GPAIRS * HDIM];
    u64 kacc [GPAIRS * HDIM];
    u64 dX   [GPAIRS * 3 * CDIM];    // [p][e][c]
    u64 bf2s [CH];                   // splatted
    u64 bf1s [HDIM];                 // splatted
    u64 s16  [GPAIRS * 16];
    ulonglong2 wf1p[16 * HDIM];      // [i2][j1]: {splat(w[2i2][j1]), splat(w[2i2+1][j1])}
    float wo1[16 * HDIM];
    float bo1[16];
    float wo2[3 * 16];
    float bo2[3];
    float winit[HDIM * CDIM];
    float binit[HDIM];
};

__global__ void __launch_bounds__(THREADS, 2)
cde_kernel(const float* __restrict__ x,
           const float* __restrict__ Winit, const float* __restrict__ binit,
           const float* __restrict__ Wf1,   const float* __restrict__ bf1,
           const float* __restrict__ Wf2,   const float* __restrict__ bf2,
           const float* __restrict__ Wo1,   const float* __restrict__ bo1,
           const float* __restrict__ Wo2,   const float* __restrict__ bo2,
           float* __restrict__ out)
{
    extern __shared__ char smraw[];
    SM& s = *reinterpret_cast<SM*>(smraw);
    const int tid   = threadIdx.x;
    const int bbase = blockIdx.x * BT;
    const int pbase = blockIdx.x * GPAIRS;   // global pair index base

    // layer-2 role: j2 (output unit), par (k-half / lane parity)
    const int par = tid & 1;
    const int j2  = tid >> 1;        // 0..223
    const int c2  = j2 % CDIM;

    // ---- load small weights into shared ----
    for (int idx = tid; idx < 16 * HDIM; idx += THREADS){
        int i2 = idx >> 5, j1 = idx & 31;
        float w0 = Wf1[j1 * HDIM + 2 * i2];
        float w1 = Wf1[j1 * HDIM + 2 * i2 + 1];
        ulonglong2 v; v.x = pk2(w0, w0); v.y = pk2(w1, w1);
        s.wf1p[idx] = v;
    }
    for (int i = tid; i < HDIM; i += THREADS){ float v = bf1[i]; s.bf1s[i] = pk2(v, v); }
    for (int i = tid; i < CH;   i += THREADS){ float v = bf2[i]; s.bf2s[i] = pk2(v, v); }
    for (int i = tid; i < 16 * HDIM; i += THREADS) s.wo1[i] = Wo1[i];
    if (tid < 16) s.bo1[tid] = bo1[tid];
    for (int i = tid; i < 48; i += THREADS) s.wo2[i] = Wo2[i];
    if (tid < 3) s.bo2[tid] = bo2[tid];
    for (int i = tid; i < HDIM * CDIM; i += THREADS) s.winit[i] = Winit[i];
    if (tid < HDIM) s.binit[tid] = binit[tid];

    // ---- diffs -> global scratch: g_diffs[pbase+p][l][c] ----
    for (int idx = tid; idx < GPAIRS * 63 * CDIM; idx += THREADS){
        int p = idx / (63 * CDIM);
        int r = idx - p * 63 * CDIM;
        int l = r / CDIM;
        int c = r - l * CDIM;
        int b0 = bbase + 2 * p;
        const float* x0 = x + ((size_t)b0 * LSEQ + l) * CDIM + c;
        const float* x1 = x0 + (size_t)LSEQ * CDIM;
        g_diffs[(size_t)(pbase + p) * 63 * CDIM + l * CDIM + c] =
            pk2(x0[CDIM] - x0[0], x1[CDIM] - x1[0]);
    }

    // ---- half-K weight slice straight from gmem (one-time) ----
    u64 wr[16];
    #pragma unroll
    for (int i = 0; i < 16; i++){
        float w = Wf2[j2 * HDIM + par * 16 + i];
        wr[i] = pk2(w, w);
    }

    // ---- z0 = x[:,0] @ Winit.T + binit ----
    __syncthreads();
    if (tid < GPAIRS * HDIM){
        int p = tid >> 5, j = tid & 31;
        int b0 = bbase + 2 * p;
        const float* x0 = x + (size_t)b0 * LSEQ * CDIM;
        const float* x1 = x0 + (size_t)LSEQ * CDIM;
        float a0 = s.binit[j], a1 = a0;
        #pragma unroll
        for (int c = 0; c < CDIM; c++){
            float w = s.winit[j * CDIM + c];
            a0 = fmaf(x0[c], w, a0);
            a1 = fmaf(x1[c], w, a1);
        }
        s.z[tid] = pk2(a0, a1);
    }
    __syncthreads();

    const u64 neg1 = pk2(-1.f, -1.f);
    const u64 two2 = pk2(2.f, 2.f);
    const u64 qh2  = pk2(0.25f, 0.25f);            // 0.5*h
    const u64 hh2  = pk2(HSTEP, HSTEP);
    const u64 h62  = pk2(HSTEP / 6.f, HSTEP / 6.f);
    const u64 bb   = (par == 0) ? s.bf2s[j2] : 0ULL;   // bias once per j2

    // ================= main time loop =================
    for (int st = 0; st < NSTEP; st++){
        float t0 = (float)st * HSTEP;

        // dX at e=0 (t0), e=1 (t0+0.25), e=2 (t0+0.5) — reads diffs from L2.
        // Ordered vs layer-2 readers by the barrier after layer 1.
        if (tid < GPAIRS * 3 * CDIM){
            int p = tid / (3 * CDIM);
            int r = tid - p * 3 * CDIM;
            int e = r / CDIM;
            int c = r - e * CDIM;
            float t = t0 + 0.25f * (float)e;
            int idx = (int)t; if (idx > 62) idx = 62;
            float f = t - (float)idx;
            int im = idx > 0 ? idx - 1 : 0;
            const u64* dp = g_diffs + (size_t)(pbase + p) * 63 * CDIM;
            u64 D = dp[idx * CDIM + c];
            u64 M = dp[im  * CDIM + c];
            float q = f * (4.f - 3.f * f);
            u64 dm = fma2(M, neg1, D);             // D - M
            s.dX[(p * 3 + e) * CDIM + c] = fma2(dm, pk2(q, q), M);
        }

        #pragma unroll
        for (int sub = 0; sub < 4; sub++){
            const int e = (sub == 0) ? 0 : ((sub == 3) ? 2 : 1);
            const u64* zin = (sub == 0) ? s.z : s.ztmp;

            // ---- layer 1: h1 = softplus(zin @ Wf1.T + bf1) ---- (256 threads)
            if (tid < GPAIRS * HDIM){
                int p = tid >> 5, j1 = tid & 31;
                const ulonglong2* zp2 = reinterpret_cast<const ulonglong2*>(zin + p * HDIM);
                u64 acc  = s.bf1s[j1];
                u64 acc2 = 0ULL;
                #pragma unroll
                for (int i2 = 0; i2 < 16; i2++){
                    ulonglong2 zv = zp2[i2];
                    ulonglong2 wv = s.wf1p[i2 * HDIM + j1];
                    acc  = fma2(zv.x, wv.x, acc);
                    acc2 = fma2(zv.y, wv.y, acc2);
                }
                acc = add2(acc, acc2);
                float2 f = upk2(acc);
                s.h1[tid] = pk2(softplus1(f.x), softplus1(f.y));
            }
            __syncthreads();

            // ---- layer 2 (half-K + warp shuffle combine) ---- (all 448)
            // Duo (pA, pB): both parities compute partial dots for both pairs;
            // one shfl_xor(1) exchange gives even lane the full pA sum and odd
            // lane the full pB sum -> tanh/dX/store at full lane utilization.
            #pragma unroll
            for (int pp = 0; pp < GPAIRS / 2; pp++){
                const int pA = pp, pB = pp + GPAIRS / 2;
                const ulonglong2* hA =
                    reinterpret_cast<const ulonglong2*>(s.h1 + pA * HDIM) + par * 8;
                const ulonglong2* hB =
                    reinterpret_cast<const ulonglong2*>(s.h1 + pB * HDIM) + par * 8;
                u64 aA = bb, aA2 = 0ULL, aB = bb, aB2 = 0ULL;
                #pragma unroll
                for (int i2 = 0; i2 < 8; i2++){
                    ulonglong2 ha = hA[i2];
                    ulonglong2 hb = hB[i2];
                    aA  = fma2(ha.x, wr[2 * i2],     aA);
                    aA2 = fma2(ha.y, wr[2 * i2 + 1], aA2);
                    aB  = fma2(hb.x, wr[2 * i2],     aB);
                    aB2 = fma2(hb.y, wr[2 * i2 + 1], aB2);
                }
                aA = add2(aA, aA2);
                aB = add2(aB, aB2);
                u64 send = par ? aA : aB;
                u64 recv = __shfl_xor_sync(0xFFFFFFFFu, send, 1);
                u64 full = add2(par ? aB : aA, recv);
                int pm   = par ? pB : pA;
                u64 t = tanh2v(full);
                s.g[pm * CH + j2] = mul2(t, s.dX[(pm * 3 + e) * CDIM + c2]);
            }
            __syncthreads();

            // ---- reduce over c (7) + RK4 state update ---- (256 threads)
            if (tid < GPAIRS * HDIM){
                int p = tid >> 5, hh = tid & 31;
                const u64* gp = s.g + p * CH + hh * CDIM;
                u64 k = add2(add2(add2(gp[0], gp[1]), add2(gp[2], gp[3])),
                             add2(add2(gp[4], gp[5]), gp[6]));
                u64 zc = s.z[tid];
                if (sub == 0){
                    s.kacc[tid] = k;
                    s.ztmp[tid] = fma2(k, qh2, zc);
                } else if (sub == 1){
                    s.kacc[tid] = fma2(k, two2, s.kacc[tid]);
                    s.ztmp[tid] = fma2(k, qh2, zc);
                } else if (sub == 2){
                    s.kacc[tid] = fma2(k, two2, s.kacc[tid]);
                    s.ztmp[tid] = fma2(k, hh2, zc);
                } else {
                    u64 ka = add2(s.kacc[tid], k);
                    s.z[tid] = fma2(ka, h62, zc);
                }
            }
            __syncthreads();
        }
    }

    // ================= output head =================
    // s16 = softplus(z @ Wo1.T + bo1)
    if (tid < GPAIRS * 16){
        int p = tid >> 4, q = tid & 15;
        float b = s.bo1[q];
        u64 acc = pk2(b, b);
        const u64* zp = s.z + p * HDIM;
        #pragma unroll
        for (int i = 0; i < HDIM; i++){
            float w = s.wo1[q * HDIM + i];
            acc = fma2(zp[i], pk2(w, w), acc);
        }
        float2 f = upk2(acc);
        s.s16[tid] = pk2(softplus1(f.x), softplus1(f.y));
    }
    __syncthreads();
    // out = s16 @ Wo2.T + bo2
    if (tid < GPAIRS * 3){
        int p = tid / 3, o = tid - p * 3;
        float b = s.bo2[o];
        u64 acc = pk2(b, b);
        const u64* sp = s.s16 + p * 16;
        #pragma unroll
        for (int q = 0; q < 16; q++){
            float w = s.wo2[o * 16 + q];
            acc = fma2(sp[q], pk2(w, w), acc);
        }
        float2 r = upk2(acc);
        int b0 = bbase + 2 * p;
        out[(size_t)b0 * 3 + o]       = r.x;
        out[(size_t)(b0 + 1) * 3 + o] = r.y;
    }
}

// Inputs (metadata order):
// 0 cde_src (4096,64,7) | 1 W_init (32,7) | 2 b_init (32) | 3 Wf1 (32,32) | 4 bf1 (32)
// 5 Wf2 (224,32) | 6 bf2 (224) | 7 Wo1 (16,32) | 8 bo1 (16) | 9 Wo2 (3,16) | 10 bo2 (3)
extern "C" void kernel_launch(void* const* d_in, const int* in_sizes, int n_in,
                              void* d_out, int out_size)
{
    const float* x     = (const float*)d_in[0];
    const float* Winit = (const float*)d_in[1];
    const float* binit = (const float*)d_in[2];
    const float* Wf1   = (const float*)d_in[3];
    const float* bf1   = (const float*)d_in[4];
    const float* Wf2   = (const float*)d_in[5];
    const float* bf2   = (const float*)d_in[6];
    const float* Wo1   = (const float*)d_in[7];
    const float* bo1   = (const float*)d_in[8];
    const float* Wo2   = (const float*)d_in[9];
    const float* bo2   = (const float*)d_in[10];

    const int B    = in_sizes[0] / (LSEQ * CDIM);   // 4096
    const int grid = B / BT;                        // 256

    size_t shmem = sizeof(SM);
    cudaFuncSetAttribute(cde_kernel, cudaFuncAttributeMaxDynamicSharedMemorySize, (int)shmem);
    cde_kernel<<<grid, THREADS, shmem>>>(x, Winit, binit, Wf1, bf1, Wf2, bf2,
                                         Wo1, bo1, Wo2, bo2, (float*)d_out);
}

// round 13
// speedup vs baseline: 1.6461x; 1.6461x over previous
#include <cuda_runtime.h>
#include <cstdint>

// Problem constants (B=4096, L=64, C=7, H=32, K=2)
#define LSEQ     64
#define CDIM     7
#define HDIM     32
#define CH       224          // C*H
#define NSTEP    126          // (L-1)*K
#define HSTEP    0.5f
#define BT       32           // batch per CTA
#define PAIRS    16           // BT/2 (f32x2 packing)
#define THREADS  448
#define GSIZE    224          // threads per sync group
#define GPAIRS   8            // pairs per group

typedef unsigned long long u64;

// ---------- packed f32x2 helpers ----------
__device__ __forceinline__ u64 pk2(float a, float b){
    u64 r; asm("mov.b64 %0,{%1,%2};" : "=l"(r) : "f"(a), "f"(b)); return r;
}
__device__ __forceinline__ float2 upk2(u64 v){
    float2 f; asm("mov.b64 {%0,%1},%2;" : "=f"(f.x), "=f"(f.y) : "l"(v)); return f;
}
__device__ __forceinline__ u64 fma2(u64 a, u64 b, u64 c){
    u64 d; asm("fma.rn.f32x2 %0,%1,%2,%3;" : "=l"(d) : "l"(a), "l"(b), "l"(c)); return d;
}
__device__ __forceinline__ u64 add2(u64 a, u64 b){
    u64 d; asm("add.rn.f32x2 %0,%1,%2;" : "=l"(d) : "l"(a), "l"(b)); return d;
}
__device__ __forceinline__ u64 mul2(u64 a, u64 b){
    u64 d; asm("mul.rn.f32x2 %0,%1,%2;" : "=l"(d) : "l"(a), "l"(b)); return d;
}

__device__ __forceinline__ float softplus1(float x){
    return (x > 20.f) ? x : __logf(1.f + __expf(x));
}
__device__ __forceinline__ float tanh1(float x){
    float e = __expf(2.f * x);
    return 1.f - __fdividef(2.f, e + 1.f);
}
__device__ __forceinline__ u64 tanh2v(u64 v){
    float2 f = upk2(v); return pk2(tanh1(f.x), tanh1(f.y));
}

// group-local barrier: ids 1 and 2, 224 threads each
__device__ __forceinline__ void barg(int gid){
    asm volatile("bar.sync %0, %1;" :: "r"(gid + 1), "r"(GSIZE) : "memory");
}

// ---------- shared memory layout ----------
struct __align__(16) SM {
    u64 diffs[PAIRS * 63 * CDIM];  // [p][l][c]  packed (b0,b1)
    u64 g    [PAIRS * CH];         // layer-2 scratch [p][c][h]; Wf2 staging at init
    u64 h1   [PAIRS * HDIM];
    u64 z    [PAIRS * HDIM];
    u64 ztmp [PAIRS * HDIM];
    u64 kacc [PAIRS * HDIM];
    u64 dX   [PAIRS * 3 * CDIM];   // [p][e][c]
    u64 bf1s [HDIM];               // splatted
    u64 bf2s [CH];                 // splatted, natural j order
    u64 s16  [PAIRS * 16];
    float wf1t[HDIM * HDIM];       // [i][j1]: lane j1 -> 4B stride, conflict-free
    float wo1[16 * HDIM];
    float bo1[16];
    float wo2[3 * 16];
    float bo2[3];
    float winit[HDIM * CDIM];
    float binit[HDIM];
};

__global__ void __launch_bounds__(THREADS, 1)
cde_kernel(const float* __restrict__ x,
           const float* __restrict__ Winit, const float* __restrict__ binit,
           const float* __restrict__ Wf1,   const float* __restrict__ bf1,
           const float* __restrict__ Wf2,   const float* __restrict__ bf2,
           const float* __restrict__ Wo1,   const float* __restrict__ bo1,
           const float* __restrict__ Wo2,   const float* __restrict__ bo2,
           float* __restrict__ out)
{
    extern __shared__ char smraw[];
    SM& s = *reinterpret_cast<SM*>(smraw);
    const int tid   = threadIdx.x;
    const int bbase = blockIdx.x * BT;
    const int gid   = tid / GSIZE;      // 0 or 1
    const int gtid  = tid - gid * GSIZE;
    const int pg    = gid * GPAIRS;     // group pair base

    // ---- load small weights into shared ----
    for (int i = tid; i < HDIM * HDIM; i += THREADS){
        int j = i / HDIM, ii = i % HDIM;
        s.wf1t[ii * HDIM + j] = Wf1[i];              // transposed [i][j]
    }
    for (int i = tid; i < HDIM; i += THREADS){ float v = bf1[i]; s.bf1s[i] = pk2(v, v); }
    for (int i = tid; i < CH;   i += THREADS){ float v = bf2[i]; s.bf2s[i] = pk2(v, v); }
    for (int i = tid; i < 16 * HDIM; i += THREADS) s.wo1[i] = Wo1[i];
    if (tid < 16) s.bo1[tid] = bo1[tid];
    for (int i = tid; i < 48; i += THREADS) s.wo2[i] = Wo2[i];
    if (tid < 3) s.bo2[tid] = bo2[tid];
    for (int i = tid; i < HDIM * CDIM; i += THREADS) s.winit[i] = Winit[i];
    if (tid < HDIM) s.binit[tid] = binit[tid];

    // ---- diffs[p][l][c] = x[b,l+1,c] - x[b,l,c], packed over (b0,b1) ----
    for (int idx = tid; idx < PAIRS * 63 * CDIM; idx += THREADS){
        int p = idx / (63 * CDIM);
        int r = idx - p * 63 * CDIM;
        int l = r / CDIM;
        int c = r - l * CDIM;
        int b0 = bbase + 2 * p;
        const float* x0 = x + ((size_t)b0 * LSEQ + l) * CDIM + c;
        const float* x1 = x0 + (size_t)LSEQ * CDIM;
        s.diffs[idx] = pk2(x0[CDIM] - x0[0], x1[CDIM] - x1[0]);
    }

    // ---- stage Wf2 (coalesced) into g region ----
    {
        float* wstage = reinterpret_cast<float*>(s.g);
        for (int i = tid; i < CH * HDIM; i += THREADS) wstage[i] = Wf2[i];
    }
    __syncthreads();

    // ---- z0 = x[:,0] @ Winit.T + binit ----
    for (int cell = tid; cell < PAIRS * HDIM; cell += THREADS){
        int p = cell >> 5, j = cell & 31;
        int b0 = bbase + 2 * p;
        const float* x0 = x + (size_t)b0 * LSEQ * CDIM;
        const float* x1 = x0 + (size_t)LSEQ * CDIM;
        float a0 = s.binit[j], a1 = a0;
        #pragma unroll
        for (int c = 0; c < CDIM; c++){
            float w = s.winit[j * CDIM + c];
            a0 = fmaf(x0[c], w, a0);
            a1 = fmaf(x1[c], w, a1);
        }
        s.z[cell] = pk2(a0, a1);
    }

    // ---- layer-2 role: j2 = c*32 + h (warp-uniform c!), natural row jnat = h*7+c ----
    const int c2   = gtid >> 5;        // 0..6, uniform within each warp
    const int h2   = gtid & 31;        // lane
    const int jnat = h2 * CDIM + c2;   // row in Wf2 / bf2
    u64 wr[HDIM];
    {
        const float* wstage = reinterpret_cast<const float*>(s.g);
        #pragma unroll
        for (int i = 0; i < HDIM; i++){
            float w = wstage[jnat * HDIM + i];
            wr[i] = pk2(w, w);
        }
    }
    __syncthreads();   // g region now free for layer-2 scratch

    const u64 neg1 = pk2(-1.f, -1.f);
    const u64 two2 = pk2(2.f, 2.f);
    const u64 qh2  = pk2(0.25f, 0.25f);            // 0.5*h
    const u64 hh2  = pk2(HSTEP, HSTEP);
    const u64 h62  = pk2(HSTEP / 6.f, HSTEP / 6.f);
    const u64 bb   = s.bf2s[jnat];

    // ================= main time loop (group-local sync only) =================
    for (int st = 0; st < NSTEP; st++){
        float t0 = (float)st * HSTEP;

        // dX for this group's pairs at e=0,1,2. Ordered vs layer-2 readers by
        // the barrier after layer 1.
        if (gtid < GPAIRS * 3 * CDIM){
            int pl = gtid / (3 * CDIM);
            int r  = gtid - pl * 3 * CDIM;
            int e  = r / CDIM;
            int c  = r - e * CDIM;
            int p  = pg + pl;
            float t = t0 + 0.25f * (float)e;
            int idx = (int)t; if (idx > 62) idx = 62;
            float f = t - (float)idx;
            int im = idx > 0 ? idx - 1 : 0;
            u64 D = s.diffs[(p * 63 + idx) * CDIM + c];
            u64 M = s.diffs[(p * 63 + im ) * CDIM + c];
            float q = f * (4.f - 3.f * f);
            u64 dm = fma2(M, neg1, D);             // D - M
            s.dX[(p * 3 + e) * CDIM + c] = fma2(dm, pk2(q, q), M);
        }

        #pragma unroll
        for (int sub = 0; sub < 4; sub++){
            const int e = (sub == 0) ? 0 : ((sub == 3) ? 2 : 1);
            const u64* zin = (sub == 0) ? s.z : s.ztmp;

            // ---- layer 1: h1 = softplus(zin @ Wf1.T + bf1) ----
            // z: 128-bit uniform broadcast (1 wf). Wf1: float, 4B lane stride (1 wf).
            for (int cell = gtid; cell < GPAIRS * HDIM; cell += GSIZE){
                int p = pg + (cell >> 5), j1 = cell & 31;
                const ulonglong2* zp2 = reinterpret_cast<const ulonglong2*>(zin + p * HDIM);
                float b0 = 0.f, b1 = 0.f, d0 = 0.f, d1 = 0.f;
                #pragma unroll
                for (int i2 = 0; i2 < 16; i2++){
                    ulonglong2 zv = zp2[i2];
                    float w0 = s.wf1t[(2 * i2)     * HDIM + j1];
                    float w1 = s.wf1t[(2 * i2 + 1) * HDIM + j1];
                    float2 za = upk2(zv.x);
                    float2 zb = upk2(zv.y);
                    b0 = fmaf(za.x, w0, b0);  b1 = fmaf(za.y, w0, b1);
                    d0 = fmaf(zb.x, w1, d0);  d1 = fmaf(zb.y, w1, d1);
                }
                float bias = __uint_as_float((unsigned)(s.bf1s[j1] & 0xFFFFFFFFu));
                float a0 = b0 + d0 + bias;
                float a1 = b1 + d1 + bias;
                s.h1[p * HDIM + j1] = pk2(softplus1(a0), softplus1(a1));
            }
            barg(gid);

            // ---- layer 2: g[p][c2][h2] = tanh(h1 @ Wf2.T + bf2)*dX[p][e][c2] ----
            {
                #pragma unroll
                for (int pp = 0; pp < GPAIRS; pp++){
                    const int p = pg + pp;
                    const ulonglong2* hp2 =
                        reinterpret_cast<const ulonglong2*>(s.h1 + p * HDIM);
                    u64 acc  = bb;
                    u64 acc2 = 0ULL;
                    #pragma unroll
                    for (int i2 = 0; i2 < 16; i2++){
                        ulonglong2 hv = hp2[i2];            // uniform -> broadcast
                        acc  = fma2(hv.x, wr[2 * i2],     acc);
                        acc2 = fma2(hv.y, wr[2 * i2 + 1], acc2);
                    }
                    acc = add2(acc, acc2);
                    u64 v = mul2(tanh2v(acc), s.dX[(p * 3 + e) * CDIM + c2]);
                    s.g[p * CH + c2 * HDIM + h2] = v;   // [p][c][h], 8B stride
                }
            }
            barg(gid);

            // ---- reduce over c (7, now 2 wf per c) + RK4 state update ----
            for (int cell = gtid; cell < GPAIRS * HDIM; cell += GSIZE){
                int p = pg + (cell >> 5), hh = cell & 31;
                int zi = p * HDIM + hh;
                const u64* gp = s.g + p * CH + hh;      // lane stride 8B per c-slice
                u64 k = add2(add2(add2(gp[0 * HDIM], gp[1 * HDIM]),
                                  add2(gp[2 * HDIM], gp[3 * HDIM])),
                             add2(add2(gp[4 * HDIM], gp[5 * HDIM]), gp[6 * HDIM]));
                u64 zc = s.z[zi];
                if (sub == 0){
                    s.kacc[zi] = k;
                    s.ztmp[zi] = fma2(k, qh2, zc);
                } else if (sub == 1){
                    s.kacc[zi] = fma2(k, two2, s.kacc[zi]);
                    s.ztmp[zi] = fma2(k, qh2, zc);
                } else if (sub == 2){
                    s.kacc[zi] = fma2(k, two2, s.kacc[zi]);
                    s.ztmp[zi] = fma2(k, hh2, zc);
                } else {
                    u64 ka = add2(s.kacc[zi], k);
                    s.z[zi] = fma2(ka, h62, zc);
                }
            }
            barg(gid);
        }
    }

    __syncthreads();

    // ================= output head =================
    // s16 = softplus(z @ Wo1.T + bo1)
    for (int cell = tid; cell < PAIRS * 16; cell += THREADS){
        int p = cell >> 4, q = cell & 15;
        float b = s.bo1[q];
        u64 acc = pk2(b, b);
        const u64* zp = s.z + p * HDIM;
        #pragma unroll
        for (int i = 0; i < HDIM; i++){
            float w = s.wo1[q * HDIM + i];
            acc = fma2(zp[i], pk2(w, w), acc);
        }
        float2 f = upk2(acc);
        s.s16[cell] = pk2(softplus1(f.x), softplus1(f.y));
    }
    __syncthreads();
    // out = s16 @ Wo2.T + bo2
    for (int cell = tid; cell < PAIRS * 3; cell += THREADS){
        int p = cell / 3, o = cell - p * 3;
        float b = s.bo2[o];
        u64 acc = pk2(b, b);
        const u64* sp = s.s16 + p * 16;
        #pragma unroll
        for (int q = 0; q < 16; q++){
            float w = s.wo2[o * 16 + q];
            acc = fma2(sp[q], pk2(w, w), acc);
        }
        float2 r = upk2(acc);
        int b0 = bbase + 2 * p;
        out[(size_t)b0 * 3 + o]       = r.x;
        out[(size_t)(b0 + 1) * 3 + o] = r.y;
    }
}

// Inputs (metadata order):
// 0 cde_src (4096,64,7) | 1 W_init (32,7) | 2 b_init (32) | 3 Wf1 (32,32) | 4 bf1 (32)
// 5 Wf2 (224,32) | 6 bf2 (224) | 7 Wo1 (16,32) | 8 bo1 (16) | 9 Wo2 (3,16) | 10 bo2 (3)
extern "C" void kernel_launch(void* const* d_in, const int* in_sizes, int n_in,
                              void* d_out, int out_size)
{
    const float* x     = (const float*)d_in[0];
    const float* Winit = (const float*)d_in[1];
    const float* binit = (const float*)d_in[2];
    const float* Wf1   = (const float*)d_in[3];
    const float* bf1   = (const float*)d_in[4];
    const float* Wf2   = (const float*)d_in[5];
    const float* bf2   = (const float*)d_in[6];
    const float* Wo1   = (const float*)d_in[7];
    const float* bo1   = (const float*)d_in[8];
    const float* Wo2   = (const float*)d_in[9];
    const float* bo2   = (const float*)d_in[10];

    const int B    = in_sizes[0] / (LSEQ * CDIM);   // 4096
    const int grid = B / BT;                        // 128

    size_t shmem = sizeof(SM);
    cudaFuncSetAttribute(cde_kernel, cudaFuncAttributeMaxDynamicSharedMemorySize, (int)shmem);
    cde_kernel<<<grid, THREADS, shmem>>>(x, Winit, binit, Wf1, bf1, Wf2, bf2,
                                         Wo1, bo1, Wo2, bo2, (float*)d_out);
}

// round 14
// speedup vs baseline: 1.8353x; 1.1150x over previous
#include <cuda_runtime.h>
#include <cstdint>

// Problem constants (B=4096, L=64, C=7, H=32, K=2)
#define LSEQ     64
#define CDIM     7
#define HDIM     32
#define CH       224          // C*H
#define NSTEP    126          // (L-1)*K
#define HSTEP    0.5f
#define BT       28           // batch per CTA (14 pairs)
#define PAIRS    14
#define THREADS  448
#define GSIZE    224          // threads per sync group
#define GPAIRS   7            // pairs per group

typedef unsigned long long u64;

// ---------- packed f32x2 helpers ----------
__device__ __forceinline__ u64 pk2(float a, float b){
    u64 r; asm("mov.b64 %0,{%1,%2};" : "=l"(r) : "f"(a), "f"(b)); return r;
}
__device__ __forceinline__ float2 upk2(u64 v){
    float2 f; asm("mov.b64 {%0,%1},%2;" : "=f"(f.x), "=f"(f.y) : "l"(v)); return f;
}
__device__ __forceinline__ u64 fma2(u64 a, u64 b, u64 c){
    u64 d; asm("fma.rn.f32x2 %0,%1,%2,%3;" : "=l"(d) : "l"(a), "l"(b), "l"(c)); return d;
}
__device__ __forceinline__ u64 add2(u64 a, u64 b){
    u64 d; asm("add.rn.f32x2 %0,%1,%2;" : "=l"(d) : "l"(a), "l"(b)); return d;
}
__device__ __forceinline__ u64 mul2(u64 a, u64 b){
    u64 d; asm("mul.rn.f32x2 %0,%1,%2;" : "=l"(d) : "l"(a), "l"(b)); return d;
}

__device__ __forceinline__ float softplus1(float x){
    return (x > 20.f) ? x : __logf(1.f + __expf(x));
}
__device__ __forceinline__ float tanh1(float x){
    float e = __expf(2.f * x);
    return 1.f - __fdividef(2.f, e + 1.f);
}
__device__ __forceinline__ u64 tanh2v(u64 v){
    float2 f = upk2(v); return pk2(tanh1(f.x), tanh1(f.y));
}

// group-local barrier: ids 1 and 2, 224 threads each
__device__ __forceinline__ void barg(int gid){
    asm volatile("bar.sync %0, %1;" :: "r"(gid + 1), "r"(GSIZE) : "memory");
}

// ---------- shared memory layout ----------
struct __align__(16) SM {
    u64 diffs[PAIRS * 63 * CDIM];  // [p][l][c]; also Wf2 staging at init (49392B >= 28672B)
    u64 g    [PAIRS * CH];         // layer-2 scratch [p][c][h]
    u64 h1   [PAIRS * HDIM];
    u64 z    [PAIRS * HDIM];
    u64 ztmp [PAIRS * HDIM];
    u64 kacc [PAIRS * HDIM];
    u64 dX   [PAIRS * 3 * CDIM];   // [p][e][c]
    u64 bf2s [CH];                 // splatted, natural j order
    u64 s16  [PAIRS * 16];
    float wf1t[HDIM * HDIM];       // [i][j1]: lane j1 -> 4B stride, conflict-free
    float bf1f[HDIM];
    float wo1[16 * HDIM];
    float bo1[16];
    float wo2[3 * 16];
    float bo2[3];
    float winit[HDIM * CDIM];
    float binit[HDIM];
};

__global__ void __launch_bounds__(THREADS, 1)
cde_kernel(const float* __restrict__ x,
           const float* __restrict__ Winit, const float* __restrict__ binit,
           const float* __restrict__ Wf1,   const float* __restrict__ bf1,
           const float* __restrict__ Wf2,   const float* __restrict__ bf2,
           const float* __restrict__ Wo1,   const float* __restrict__ bo1,
           const float* __restrict__ Wo2,   const float* __restrict__ bo2,
           float* __restrict__ out, int Btot)
{
    extern __shared__ char smraw[];
    SM& s = *reinterpret_cast<SM*>(smraw);
    const int tid   = threadIdx.x;
    const int bbase = blockIdx.x * BT;
    const int gid   = tid / GSIZE;      // 0 or 1
    const int gtid  = tid - gid * GSIZE;
    const int pg    = gid * GPAIRS;     // group pair base

    // ---- phase 1: stage weights (Wf2 into diffs region) ----
    {
        float* wstage = reinterpret_cast<float*>(s.diffs);
        for (int i = tid; i < CH * HDIM; i += THREADS) wstage[i] = Wf2[i];
    }
    for (int i = tid; i < HDIM * HDIM; i += THREADS){
        int j = i / HDIM, ii = i % HDIM;
        s.wf1t[ii * HDIM + j] = Wf1[i];              // transposed [i][j]
    }
    if (tid < HDIM) s.bf1f[tid] = bf1[tid];
    for (int i = tid; i < CH;   i += THREADS){ float v = bf2[i]; s.bf2s[i] = pk2(v, v); }
    for (int i = tid; i < 16 * HDIM; i += THREADS) s.wo1[i] = Wo1[i];
    if (tid < 16) s.bo1[tid] = bo1[tid];
    for (int i = tid; i < 48; i += THREADS) s.wo2[i] = Wo2[i];
    if (tid < 3) s.bo2[tid] = bo2[tid];
    for (int i = tid; i < HDIM * CDIM; i += THREADS) s.winit[i] = Winit[i];
    if (tid < HDIM) s.binit[tid] = binit[tid];
    __syncthreads();

    // ---- phase 2: read per-thread Wf2 slice + z0 ----
    // layer-2 role: j2 = c*32 + h (warp-uniform c), natural row jnat = h*7+c
    const int c2   = gtid >> 5;        // 0..6, uniform within each warp
    const int h2   = gtid & 31;        // lane
    const int jnat = h2 * CDIM + c2;   // row in Wf2 / bf2
    u64 wr[HDIM];
    {
        const float* wstage = reinterpret_cast<const float*>(s.diffs);
        #pragma unroll
        for (int i = 0; i < HDIM; i++){
            float w = wstage[jnat * HDIM + i];
            wr[i] = pk2(w, w);
        }
    }
    // z0 = x[:,0] @ Winit.T + binit   (448 cells = THREADS exactly)
    {
        int p = tid >> 5, j = tid & 31;
        int b0 = bbase + 2 * p; if (b0 > Btot - 2) b0 = Btot - 2;
        const float* x0 = x + (size_t)b0 * LSEQ * CDIM;
        const float* x1 = x0 + (size_t)LSEQ * CDIM;
        float a0 = s.binit[j], a1 = a0;
        #pragma unroll
        for (int c = 0; c < CDIM; c++){
            float w = s.winit[j * CDIM + c];
            a0 = fmaf(x0[c], w, a0);
            a1 = fmaf(x1[c], w, a1);
        }
        s.z[tid] = pk2(a0, a1);
    }
    __syncthreads();   // all wr reads done -> diffs region reusable

    // ---- phase 3: diffs[p][l][c] = x[b,l+1,c] - x[b,l,c] ----
    for (int idx = tid; idx < PAIRS * 63 * CDIM; idx += THREADS){
        int p = idx / (63 * CDIM);
        int r = idx - p * 63 * CDIM;
        int l = r / CDIM;
        int c = r - l * CDIM;
        int b0 = bbase + 2 * p; if (b0 > Btot - 2) b0 = Btot - 2;
        const float* x0 = x + ((size_t)b0 * LSEQ + l) * CDIM + c;
        const float* x1 = x0 + (size_t)LSEQ * CDIM;
        s.diffs[idx] = pk2(x0[CDIM] - x0[0], x1[CDIM] - x1[0]);
    }
    __syncthreads();

    const u64 neg1 = pk2(-1.f, -1.f);
    const u64 two2 = pk2(2.f, 2.f);
    const u64 qh2  = pk2(0.25f, 0.25f);            // 0.5*h
    const u64 hh2  = pk2(HSTEP, HSTEP);
    const u64 h62  = pk2(HSTEP / 6.f, HSTEP / 6.f);
    const u64 bb   = s.bf2s[jnat];

    // ================= main time loop (group-local sync only) =================
    for (int st = 0; st < NSTEP; st++){
        float t0 = (float)st * HSTEP;

        // dX for this group's pairs at e=0,1,2 (147 of 224 threads).
        // Ordered vs layer-2 readers by the barrier after layer 1.
        if (gtid < GPAIRS * 3 * CDIM){
            int pl = gtid / (3 * CDIM);
            int r  = gtid - pl * 3 * CDIM;
            int e  = r / CDIM;
            int c  = r - e * CDIM;
            int p  = pg + pl;
            float t = t0 + 0.25f * (float)e;
            int idx = (int)t; if (idx > 62) idx = 62;
            float f = t - (float)idx;
            int im = idx > 0 ? idx - 1 : 0;
            u64 D = s.diffs[(p * 63 + idx) * CDIM + c];
            u64 M = s.diffs[(p * 63 + im ) * CDIM + c];
            float q = f * (4.f - 3.f * f);
            u64 dm = fma2(M, neg1, D);             // D - M
            s.dX[(p * 3 + e) * CDIM + c] = fma2(dm, pk2(q, q), M);
        }

        #pragma unroll
        for (int sub = 0; sub < 4; sub++){
            const int e = (sub == 0) ? 0 : ((sub == 3) ? 2 : 1);
            const u64* zin = (sub == 0) ? s.z : s.ztmp;

            // ---- layer 1: h1 = softplus(zin @ Wf1.T + bf1) ----
            // 224 cells = GSIZE exactly: single full-width pass, no tail iter.
            {
                int p = pg + (gtid >> 5), j1 = gtid & 31;
                const ulonglong2* zp2 = reinterpret_cast<const ulonglong2*>(zin + p * HDIM);
                float b0 = 0.f, b1 = 0.f, d0 = 0.f, d1 = 0.f;
                #pragma unroll
                for (int i2 = 0; i2 < 16; i2++){
                    ulonglong2 zv = zp2[i2];
                    float w0 = s.wf1t[(2 * i2)     * HDIM + j1];
                    float w1 = s.wf1t[(2 * i2 + 1) * HDIM + j1];
                    float2 za = upk2(zv.x);
                    float2 zb = upk2(zv.y);
                    b0 = fmaf(za.x, w0, b0);  b1 = fmaf(za.y, w0, b1);
                    d0 = fmaf(zb.x, w1, d0);  d1 = fmaf(zb.y, w1, d1);
                }
                float bias = s.bf1f[j1];
                float a0 = b0 + d0 + bias;
                float a1 = b1 + d1 + bias;
                s.h1[p * HDIM + j1] = pk2(softplus1(a0), softplus1(a1));
            }
            barg(gid);

            // ---- layer 2: g[p][c2][h2] = tanh(h1 @ Wf2.T + bf2)*dX[p][e][c2] ----
            {
                #pragma unroll
                for (int pp = 0; pp < GPAIRS; pp++){
                    const int p = pg + pp;
                    const ulonglong2* hp2 =
                        reinterpret_cast<const ulonglong2*>(s.h1 + p * HDIM);
                    u64 acc  = bb;
                    u64 acc2 = 0ULL;
                    #pragma unroll
                    for (int i2 = 0; i2 < 16; i2++){
                        ulonglong2 hv = hp2[i2];            // uniform -> broadcast
                        acc  = fma2(hv.x, wr[2 * i2],     acc);
                        acc2 = fma2(hv.y, wr[2 * i2 + 1], acc2);
                    }
                    acc = add2(acc, acc2);
                    u64 v = mul2(tanh2v(acc), s.dX[(p * 3 + e) * CDIM + c2]);
                    s.g[p * CH + c2 * HDIM + h2] = v;   // [p][c][h], 8B stride
                }
            }
            barg(gid);

            // ---- reduce over c (2 wf per c) + RK4; 224 cells = GSIZE ----
            {
                int p = pg + (gtid >> 5), hh = gtid & 31;
                int zi = p * HDIM + hh;
                const u64* gp = s.g + p * CH + hh;      // 8B lane stride per c-slice
                u64 k = add2(add2(add2(gp[0 * HDIM], gp[1 * HDIM]),
                                  add2(gp[2 * HDIM], gp[3 * HDIM])),
                             add2(add2(gp[4 * HDIM], gp[5 * HDIM]), gp[6 * HDIM]));
                u64 zc = s.z[zi];
                if (sub == 0){
                    s.kacc[zi] = k;
                    s.ztmp[zi] = fma2(k, qh2, zc);
                } else if (sub == 1){
                    s.kacc[zi] = fma2(k, two2, s.kacc[zi]);
                    s.ztmp[zi] = fma2(k, qh2, zc);
                } else if (sub == 2){
                    s.kacc[zi] = fma2(k, two2, s.kacc[zi]);
                    s.ztmp[zi] = fma2(k, hh2, zc);
                } else {
                    u64 ka = add2(s.kacc[zi], k);
                    s.z[zi] = fma2(ka, h62, zc);
                }
            }
            barg(gid);
        }
    }

    __syncthreads();

    // ================= output head =================
    // s16 = softplus(z @ Wo1.T + bo1)   (224 cells)
    if (tid < PAIRS * 16){
        int p = tid >> 4, q = tid & 15;
        float b = s.bo1[q];
        u64 acc = pk2(b, b);
        const u64* zp = s.z + p * HDIM;
        #pragma unroll
        for (int i = 0; i < HDIM; i++){
            float w = s.wo1[q * HDIM + i];
            acc = fma2(zp[i], pk2(w, w), acc);
        }
        float2 f = upk2(acc);
        s.s16[tid] = pk2(softplus1(f.x), softplus1(f.y));
    }
    __syncthreads();
    // out = s16 @ Wo2.T + bo2  (store-guarded for tail CTA)
    if (tid < PAIRS * 3){
        int p = tid / 3, o = tid - p * 3;
        int b0 = bbase + 2 * p;
        if (b0 <= Btot - 2){
            float b = s.bo2[o];
            u64 acc = pk2(b, b);
            const u64* sp = s.s16 + p * 16;
            #pragma unroll
            for (int q = 0; q < 16; q++){
                float w = s.wo2[o * 16 + q];
                acc = fma2(sp[q], pk2(w, w), acc);
            }
            float2 r = upk2(acc);
            out[(size_t)b0 * 3 + o]       = r.x;
            out[(size_t)(b0 + 1) * 3 + o] = r.y;
        }
    }
}

// Inputs (metadata order):
// 0 cde_src (4096,64,7) | 1 W_init (32,7) | 2 b_init (32) | 3 Wf1 (32,32) | 4 bf1 (32)
// 5 Wf2 (224,32) | 6 bf2 (224) | 7 Wo1 (16,32) | 8 bo1 (16) | 9 Wo2 (3,16) | 10 bo2 (3)
extern "C" void kernel_launch(void* const* d_in, const int* in_sizes, int n_in,
                              void* d_out, int out_size)
{
    const float* x     = (const float*)d_in[0];
    const float* Winit = (const float*)d_in[1];
    const float* binit = (const float*)d_in[2];
    const float* Wf1   = (const float*)d_in[3];
    const float* bf1   = (const float*)d_in[4];
    const float* Wf2   = (const float*)d_in[5];
    const float* bf2   = (const float*)d_in[6];
    const float* Wo1   = (const float*)d_in[7];
    const float* bo1   = (const float*)d_in[8];
    const float* Wo2   = (const float*)d_in[9];
    const float* bo2   = (const float*)d_in[10];

    const int B    = in_sizes[0] / (LSEQ * CDIM);   // 4096
    const int grid = (B + BT - 1) / BT;             // 147

    size_t shmem = sizeof(SM);
    cudaFuncSetAttribute(cde_kernel, cudaFuncAttributeMaxDynamicSharedMemorySize, (int)shmem);
    cde_kernel<<<grid, THREADS, shmem>>>(x, Winit, binit, Wf1, bf1, Wf2, bf2,
                                         Wo1, bo1, Wo2, bo2, (float*)d_out, B);
}